// round 2
// baseline (speedup 1.0000x reference)
#include <cuda_runtime.h>

// Fixed problem structure:
//   4 nodes/graph (nodes 0..2 = jet, node 3 = muon)
//   12 directed edges/graph, edge (i,j) index within graph = 3*i + (j - (j>i))
//   H = 16, MH = 64.

#define NTHREADS 256

// ---- constant-memory layout (floats), warp-uniform weights ----
#define cL1W  0      // 64
#define cL1B  64     // 16
#define cM1W1 80     // 1024
#define cM1B1 1104   // 64
#define cM1W2 1168   // 1024
#define cM1B2 2192   // 16
#define cL2W  2208   // 64
#define cL2B  2272   // 16
#define cM2W1 2288   // 1024
#define cM2B1 3312   // 64
#define cM2W2 3376   // 1024
#define cM2B2 4400   // 16
#define cFCW1 4416   // 2048
#define cFCB1 6464   // 64
#define cFCW2 6528   // 64
#define cFCB2 6592   // 1
#define CONST_FLOATS 6593

__constant__ float C[CONST_FLOATS];
__device__ float g_stage[CONST_FLOATS];

// ---- shared memory layout (floats): only node-divergent encoder weights ----
#define JE_W1 0      // 80
#define JE_B1 80     // 16
#define JE_W2 96     // 256
#define JE_B2 352    // 16
#define MU_W1 368    // 80
#define MU_B1 448    // 16
#define MU_W2 464    // 256
#define MU_B2 720    // 16
#define SMEM_FLOATS 736

struct Params {
    const float* x;
    const float* ea;
    const float* enc[8];  // je_w1..mu_b2
    float* out;
    int G;
};

struct PackParams {
    const float* src[16]; // lin1_w..fc_b2
};

__global__ void pack_kernel(PackParams pp)
{
    const int sizes[16] = {64,16,1024,64,1024,16, 64,16,1024,64,1024,16, 2048,64,64,1};
    const int offs[16]  = {cL1W,cL1B,cM1W1,cM1B1,cM1W2,cM1B2,
                           cL2W,cL2B,cM2W1,cM2B1,cM2W2,cM2B2,
                           cFCW1,cFCB1,cFCW2,cFCB2};
    for (int a = 0; a < 16; a++) {
        const float* s = pp.src[a];
        float* d = g_stage + offs[a];
        int n = sizes[a];
        for (int i = threadIdx.x; i < n; i += blockDim.x) d[i] = s[i];
    }
}

__device__ __forceinline__ float4 ld4s(const float* p) {
    return *reinterpret_cast<const float4*>(p);
}

__device__ __forceinline__ void addv4(float* acc, float s, float4 w) {
    acc[0] = fmaf(s, w.x, acc[0]);
    acc[1] = fmaf(s, w.y, acc[1]);
    acc[2] = fmaf(s, w.z, acc[2]);
    acc[3] = fmaf(s, w.w, acc[3]);
}

__device__ __forceinline__ void addv4c(float* acc, float s, int coff) {
    acc[0] = fmaf(s, C[coff + 0], acc[0]);
    acc[1] = fmaf(s, C[coff + 1], acc[1]);
    acc[2] = fmaf(s, C[coff + 2], acc[2]);
    acc[3] = fmaf(s, C[coff + 3], acc[3]);
}

// one GINE layer + LN + relu, fully in registers; h updated in place.
// All weight offsets are compile-time constants -> uniform constant loads (LDCU).
template<int LW, int LB, int W1, int B1, int W2, int B2>
__device__ __forceinline__ void gine_ln_relu(
    float (&h)[16], int lane, int node, int graph,
    const float* __restrict__ ea)
{
    float agg[16];
#pragma unroll
    for (int d = 0; d < 16; d++) agg[d] = 0.f;

    const float* eb = ea + (long long)graph * 48;

#pragma unroll
    for (int m = 1; m < 4; m++) {
        int src = (node + m) & 3;
        int eidx = src * 3 + node - (node > src ? 1 : 0);
        float4 e4 = __ldg(reinterpret_cast<const float4*>(eb + eidx * 4));
        float ev[4] = {e4.x, e4.y, e4.z, e4.w};

        float msg[16];
#pragma unroll
        for (int d = 0; d < 16; d++) msg[d] = C[LB + d];
#pragma unroll
        for (int k = 0; k < 4; k++) {
            float ek = ev[k];
#pragma unroll
            for (int v = 0; v < 4; v++)
                addv4c(&msg[4 * v], ek, LW + k * 16 + 4 * v);
        }

        int sl = (lane & ~3) | src;
#pragma unroll
        for (int d = 0; d < 16; d++) {
            float hs = __shfl_sync(0xffffffffu, h[d], sl);
            agg[d] += fmaxf(msg[d] + hs, 0.f);
        }
    }

    float in[16];
#pragma unroll
    for (int d = 0; d < 16; d++) in[d] = h[d] + agg[d];

    float out[16];
#pragma unroll
    for (int d = 0; d < 16; d++) out[d] = C[B2 + d];

#pragma unroll
    for (int c = 0; c < 4; c++) {
        float hid[16];
#pragma unroll
        for (int d = 0; d < 16; d++) hid[d] = C[B1 + c * 16 + d];
#pragma unroll
        for (int k = 0; k < 16; k++) {
            float xk = in[k];
#pragma unroll
            for (int v = 0; v < 4; v++)
                addv4c(&hid[4 * v], xk, W1 + k * 64 + c * 16 + 4 * v);
        }
#pragma unroll
        for (int u = 0; u < 16; u++) hid[u] = fmaxf(hid[u], 0.f);
#pragma unroll
        for (int u = 0; u < 16; u++) {
            float hu = hid[u];
#pragma unroll
            for (int v = 0; v < 4; v++)
                addv4c(&out[4 * v], hu, W2 + (c * 16 + u) * 16 + 4 * v);
        }
    }

    // LayerNorm (ddof=0) + relu
    float mean = 0.f;
#pragma unroll
    for (int d = 0; d < 16; d++) mean += out[d];
    mean *= (1.f / 16.f);
    float var = 0.f;
#pragma unroll
    for (int d = 0; d < 16; d++) { float dd = out[d] - mean; var = fmaf(dd, dd, var); }
    var *= (1.f / 16.f);
    float inv = rsqrtf(var + 1e-5f);
#pragma unroll
    for (int d = 0; d < 16; d++) h[d] = fmaxf((out[d] - mean) * inv, 0.f);
}

__global__ void __launch_bounds__(NTHREADS)
gnn_kernel(Params p)
{
    __shared__ float S[SMEM_FLOATS];

    // stage encoder weights into shared
    {
        const int sizes[8] = {80,16,256,16, 80,16,256,16};
        const int offs[8]  = {JE_W1,JE_B1,JE_W2,JE_B2, MU_W1,MU_B1,MU_W2,MU_B2};
        for (int a = 0; a < 8; a++) {
            const float* src = p.enc[a];
            float* dst = S + offs[a];
            int n = sizes[a];
            for (int i = threadIdx.x; i < n; i += NTHREADS) dst[i] = src[i];
        }
    }
    __syncthreads();

    int tid = threadIdx.x;
    int lane = tid & 31;
    int node = lane & 3;
    long long total = (long long)p.G * 4;
    long long stride = (long long)gridDim.x * NTHREADS;

    for (long long slot = (long long)blockIdx.x * NTHREADS + tid;
         slot - lane < total; slot += stride)
    {
        long long gl = slot >> 2;
        int graph = (gl < p.G) ? (int)gl : (p.G - 1);

        // ---- heterogeneous encoder (shared mem, node-divergent base) ----
        float xin[5];
        {
            const float* xr = p.x + (long long)(graph * 4 + node) * 5;
#pragma unroll
            for (int k = 0; k < 5; k++) xin[k] = __ldg(xr + k);
        }
        const float* w1 = (node == 3) ? (S + MU_W1) : (S + JE_W1);
        const float* b1 = (node == 3) ? (S + MU_B1) : (S + JE_B1);
        const float* w2 = (node == 3) ? (S + MU_W2) : (S + JE_W2);
        const float* b2 = (node == 3) ? (S + MU_B2) : (S + JE_B2);

        float t[16];
#pragma unroll
        for (int v = 0; v < 4; v++) {
            float4 b = ld4s(b1 + 4 * v);
            t[4 * v + 0] = b.x; t[4 * v + 1] = b.y;
            t[4 * v + 2] = b.z; t[4 * v + 3] = b.w;
        }
#pragma unroll
        for (int k = 0; k < 5; k++) {
            float xk = xin[k];
#pragma unroll
            for (int v = 0; v < 4; v++)
                addv4(&t[4 * v], xk, ld4s(w1 + k * 16 + 4 * v));
        }
#pragma unroll
        for (int u = 0; u < 16; u++) t[u] = fmaxf(t[u], 0.f);

        float h[16];
#pragma unroll
        for (int v = 0; v < 4; v++) {
            float4 b = ld4s(b2 + 4 * v);
            h[4 * v + 0] = b.x; h[4 * v + 1] = b.y;
            h[4 * v + 2] = b.z; h[4 * v + 3] = b.w;
        }
#pragma unroll
        for (int k = 0; k < 16; k++) {
            float tk = t[k];
#pragma unroll
            for (int v = 0; v < 4; v++)
                addv4(&h[4 * v], tk, ld4s(w2 + k * 16 + 4 * v));
        }

        // ---- two GINE blocks (constant-memory weights) ----
        gine_ln_relu<cL1W, cL1B, cM1W1, cM1B1, cM1W2, cM1B2>(h, lane, node, graph, p.ea);
        gine_ln_relu<cL2W, cL2B, cM2W1, cM2B1, cM2W2, cM2B2>(h, lane, node, graph, p.ea);

        // ---- pooling (mean + max over the 4 lanes of the graph) ----
        float g[32];
#pragma unroll
        for (int d = 0; d < 16; d++) {
            float s = h[d];
            s += __shfl_xor_sync(0xffffffffu, s, 1);
            s += __shfl_xor_sync(0xffffffffu, s, 2);
            float mx = h[d];
            mx = fmaxf(mx, __shfl_xor_sync(0xffffffffu, mx, 1));
            mx = fmaxf(mx, __shfl_xor_sync(0xffffffffu, mx, 2));
            g[d] = s * 0.25f;
            g[16 + d] = mx;
        }
        // LN over 32
        {
            float mean = 0.f;
#pragma unroll
            for (int d = 0; d < 32; d++) mean += g[d];
            mean *= (1.f / 32.f);
            float var = 0.f;
#pragma unroll
            for (int d = 0; d < 32; d++) { float dd = g[d] - mean; var = fmaf(dd, dd, var); }
            var *= (1.f / 32.f);
            float inv = rsqrtf(var + 1e-5f);
#pragma unroll
            for (int d = 0; d < 32; d++) g[d] = (g[d] - mean) * inv;
        }

        // ---- FC head: 32 -> 64 -> 1, hidden split across the 4 lanes ----
        // lane's node selects 16 of the 64 hidden units; node-dependent constant
        // index would be divergent, so express as 4 static slices selected per lane.
        float acc = 0.f;
#pragma unroll
        for (int uv = 0; uv < 16; uv++) {
            // hidden unit u = node*16 + uv : compute via uniform loads by looping
            // over all 64 and predicating on ownership would quadruple work; instead
            // accept divergent constant access here (tiny: 32 MACs * 16 per node).
            int u = node * 16 + uv;
            float a = C[cFCB1 + u];
#pragma unroll
            for (int k = 0; k < 32; k++)
                a = fmaf(g[k], C[cFCW1 + k * 64 + u], a);
            acc = fmaf(fmaxf(a, 0.f), C[cFCW2 + u], acc);
        }
        acc += __shfl_xor_sync(0xffffffffu, acc, 1);
        acc += __shfl_xor_sync(0xffffffffu, acc, 2);

        if (node == 0 && slot < total)
            p.out[graph] = acc + C[cFCB2];
    }
}

extern "C" void kernel_launch(void* const* d_in, const int* in_sizes, int n_in,
                              void* d_out, int out_size)
{
    // inputs: 0 x, 1 edge_attr, 2..25 weights in reference order
    Params p;
    p.x  = (const float*)d_in[0];
    p.ea = (const float*)d_in[1];
    for (int i = 0; i < 8; i++) p.enc[i] = (const float*)d_in[2 + i]; // je_*, mu_*
    p.out = (float*)d_out;
    p.G = in_sizes[0] / 20;

    PackParams pp;
    for (int i = 0; i < 16; i++) pp.src[i] = (const float*)d_in[10 + i]; // lin1_w..fc_b2

    pack_kernel<<<1, 256>>>(pp);

    void* stage_ptr = nullptr;
    cudaGetSymbolAddress(&stage_ptr, g_stage);
    cudaMemcpyToSymbolAsync(C, stage_ptr, CONST_FLOATS * sizeof(float), 0,
                            cudaMemcpyDeviceToDevice, 0);

    long long total = (long long)p.G * 4;
    int blocks = (int)((total + NTHREADS - 1) / NTHREADS);
    if (blocks > 888) blocks = 888;
    if (blocks < 1) blocks = 1;
    gnn_kernel<<<blocks, NTHREADS>>>(p);
}

// round 3
// speedup vs baseline: 8.1275x; 8.1275x over previous
#include <cuda_runtime.h>

// Fixed problem structure:
//   4 nodes/graph (nodes 0..2 = jet, node 3 = muon)
//   12 directed edges/graph, edge (i,j) index within graph = 3*i + (j - (j>i))
//   H = 16, MH = 64.
// Mapping: warp = 8 groups of 4 lanes; group j, node = lane&3.
// NV=2: group j handles graphs base+j and base+j+8, sharing every weight load.

#define NTHREADS 256

// ---- shared memory layout (floats) ----
#define JE_W1 0      // 80
#define JE_B1 80     // 16
#define JE_W2 96     // 256
#define JE_B2 352    // 16
#define MU_W1 368    // 80
#define MU_B1 448    // 16
#define MU_W2 464    // 256
#define MU_B2 720    // 16
#define L1_W  736    // 64
#define L1_B  800    // 16
#define M1_W1 816    // 1024
#define M1_B1 1840   // 64
#define M1_W2 1904   // 1024
#define M1_B2 2928   // 16
#define L2_W  2944   // 64
#define L2_B  3008   // 16
#define M2_W1 3024   // 1024
#define M2_B1 4048   // 64
#define M2_W2 4112   // 1024
#define M2_B2 5136   // 16
#define FC_W1 5152   // 2048
#define FC_B1 7200   // 64
#define FC_W2 7264   // 64
#define SMEM_FLOATS 7328

struct Params {
    const float* x;
    const float* ea;
    const float* w[24];   // je_w1..fc_b2 in metadata order
    float* out;
    int G;
};

__device__ __forceinline__ float4 ld4s(const float* p) {
    return *reinterpret_cast<const float4*>(p);
}

__device__ __forceinline__ void addv4(float* acc, float s, float4 w) {
    acc[0] = fmaf(s, w.x, acc[0]);
    acc[1] = fmaf(s, w.y, acc[1]);
    acc[2] = fmaf(s, w.z, acc[2]);
    acc[3] = fmaf(s, w.w, acc[3]);
}

__device__ __forceinline__ void setv4(float* dst, float4 b) {
    dst[0] = b.x; dst[1] = b.y; dst[2] = b.z; dst[3] = b.w;
}

// one GINE layer + LN + relu for 2 graphs at once; h updated in place.
// e[nv][m-1] = edge_attr of edge (src=(node+m)&3 -> node) for graph nv.
__device__ __forceinline__ void gine_ln_relu2(
    float h[2][16], const float4 e[2][3], int lane, int node,
    const float* lw, const float* lb,
    const float* w1, const float* b1,
    const float* w2, const float* b2)
{
    float agg[2][16];
#pragma unroll
    for (int nv = 0; nv < 2; nv++)
#pragma unroll
        for (int d = 0; d < 16; d++) agg[nv][d] = 0.f;

#pragma unroll
    for (int m = 1; m < 4; m++) {
        int src = (node + m) & 3;
        int sl = (lane & ~3) | src;

        float msg[2][16];
#pragma unroll
        for (int v = 0; v < 4; v++) {
            float4 b = ld4s(lb + 4 * v);
            setv4(&msg[0][4 * v], b);
            setv4(&msg[1][4 * v], b);
        }
        float ev0[4] = {e[0][m-1].x, e[0][m-1].y, e[0][m-1].z, e[0][m-1].w};
        float ev1[4] = {e[1][m-1].x, e[1][m-1].y, e[1][m-1].z, e[1][m-1].w};
#pragma unroll
        for (int k = 0; k < 4; k++) {
#pragma unroll
            for (int v = 0; v < 4; v++) {
                float4 w = ld4s(lw + k * 16 + 4 * v);
                addv4(&msg[0][4 * v], ev0[k], w);
                addv4(&msg[1][4 * v], ev1[k], w);
            }
        }
#pragma unroll
        for (int d = 0; d < 16; d++) {
            float hs0 = __shfl_sync(0xffffffffu, h[0][d], sl);
            float hs1 = __shfl_sync(0xffffffffu, h[1][d], sl);
            agg[0][d] += fmaxf(msg[0][d] + hs0, 0.f);
            agg[1][d] += fmaxf(msg[1][d] + hs1, 0.f);
        }
    }

    float in[2][16];
#pragma unroll
    for (int nv = 0; nv < 2; nv++)
#pragma unroll
        for (int d = 0; d < 16; d++) in[nv][d] = h[nv][d] + agg[nv][d];

    float out[2][16];
#pragma unroll
    for (int v = 0; v < 4; v++) {
        float4 b = ld4s(b2 + 4 * v);
        setv4(&out[0][4 * v], b);
        setv4(&out[1][4 * v], b);
    }

#pragma unroll
    for (int c = 0; c < 4; c++) {
        float hid[2][16];
#pragma unroll
        for (int v = 0; v < 4; v++) {
            float4 b = ld4s(b1 + c * 16 + 4 * v);
            setv4(&hid[0][4 * v], b);
            setv4(&hid[1][4 * v], b);
        }
#pragma unroll
        for (int k = 0; k < 16; k++) {
            float x0 = in[0][k];
            float x1 = in[1][k];
#pragma unroll
            for (int v = 0; v < 4; v++) {
                float4 w = ld4s(w1 + k * 64 + c * 16 + 4 * v);
                addv4(&hid[0][4 * v], x0, w);
                addv4(&hid[1][4 * v], x1, w);
            }
        }
#pragma unroll
        for (int nv = 0; nv < 2; nv++)
#pragma unroll
            for (int u = 0; u < 16; u++) hid[nv][u] = fmaxf(hid[nv][u], 0.f);
#pragma unroll
        for (int u = 0; u < 16; u++) {
            float h0 = hid[0][u];
            float h1 = hid[1][u];
            const float* r = w2 + (c * 16 + u) * 16;
#pragma unroll
            for (int v = 0; v < 4; v++) {
                float4 w = ld4s(r + 4 * v);
                addv4(&out[0][4 * v], h0, w);
                addv4(&out[1][4 * v], h1, w);
            }
        }
    }

    // LayerNorm (ddof=0) + relu
#pragma unroll
    for (int nv = 0; nv < 2; nv++) {
        float mean = 0.f;
#pragma unroll
        for (int d = 0; d < 16; d++) mean += out[nv][d];
        mean *= (1.f / 16.f);
        float var = 0.f;
#pragma unroll
        for (int d = 0; d < 16; d++) { float dd = out[nv][d] - mean; var = fmaf(dd, dd, var); }
        var *= (1.f / 16.f);
        float inv = rsqrtf(var + 1e-5f);
#pragma unroll
        for (int d = 0; d < 16; d++) h[nv][d] = fmaxf((out[nv][d] - mean) * inv, 0.f);
    }
}

__global__ void __launch_bounds__(NTHREADS, 1)
gnn_kernel(Params p)
{
    __shared__ float S[SMEM_FLOATS];

    // stage all weights into shared
    {
        const int sizes[23] = {80,16,256,16, 80,16,256,16,
                               64,16,1024,64,1024,16,
                               64,16,1024,64,1024,16,
                               2048,64,64};
        const int offs[23]  = {JE_W1,JE_B1,JE_W2,JE_B2, MU_W1,MU_B1,MU_W2,MU_B2,
                               L1_W,L1_B,M1_W1,M1_B1,M1_W2,M1_B2,
                               L2_W,L2_B,M2_W1,M2_B1,M2_W2,M2_B2,
                               FC_W1,FC_B1,FC_W2};
        for (int a = 0; a < 23; a++) {
            const float* src = p.w[a];
            float* dst = S + offs[a];
            int n = sizes[a];
            for (int i = threadIdx.x; i < n; i += NTHREADS) dst[i] = src[i];
        }
    }
    __syncthreads();

    const float fcb2 = __ldg(p.w[23]);

    int tid = threadIdx.x;
    int lane = tid & 31;
    int node = lane & 3;
    int group = lane >> 2;
    int warpG = (int)((blockIdx.x * (unsigned)NTHREADS + tid) >> 5);

    int g0 = warpG * 16 + group;
    int g1 = g0 + 8;
    bool v0 = g0 < p.G;
    bool v1 = g1 < p.G;
    int gc0 = v0 ? g0 : (p.G - 1);
    int gc1 = v1 ? g1 : (p.G - 1);
    if (!v0 && !v1 && __ballot_sync(0xffffffffu, v0 | v1) == 0u) return;

    // ---- load node features + all edge attrs up front (regs) ----
    float xin[2][5];
    {
        const float* xr0 = p.x + (long long)(gc0 * 4 + node) * 5;
        const float* xr1 = p.x + (long long)(gc1 * 4 + node) * 5;
#pragma unroll
        for (int k = 0; k < 5; k++) { xin[0][k] = __ldg(xr0 + k); xin[1][k] = __ldg(xr1 + k); }
    }
    float4 e[2][3];
    {
        const float* eb0 = p.ea + (long long)gc0 * 48;
        const float* eb1 = p.ea + (long long)gc1 * 48;
#pragma unroll
        for (int m = 1; m < 4; m++) {
            int src = (node + m) & 3;
            int eidx = src * 3 + node - (node > src ? 1 : 0);
            e[0][m-1] = __ldg(reinterpret_cast<const float4*>(eb0 + eidx * 4));
            e[1][m-1] = __ldg(reinterpret_cast<const float4*>(eb1 + eidx * 4));
        }
    }

    // ---- heterogeneous encoder ----
    const float* w1p = (node == 3) ? (S + MU_W1) : (S + JE_W1);
    const float* b1p = (node == 3) ? (S + MU_B1) : (S + JE_B1);
    const float* w2p = (node == 3) ? (S + MU_W2) : (S + JE_W2);
    const float* b2p = (node == 3) ? (S + MU_B2) : (S + JE_B2);

    float h[2][16];
    {
        float t[2][16];
#pragma unroll
        for (int v = 0; v < 4; v++) {
            float4 b = ld4s(b1p + 4 * v);
            setv4(&t[0][4 * v], b);
            setv4(&t[1][4 * v], b);
        }
#pragma unroll
        for (int k = 0; k < 5; k++) {
            float x0 = xin[0][k], x1 = xin[1][k];
#pragma unroll
            for (int v = 0; v < 4; v++) {
                float4 w = ld4s(w1p + k * 16 + 4 * v);
                addv4(&t[0][4 * v], x0, w);
                addv4(&t[1][4 * v], x1, w);
            }
        }
#pragma unroll
        for (int nv = 0; nv < 2; nv++)
#pragma unroll
            for (int u = 0; u < 16; u++) t[nv][u] = fmaxf(t[nv][u], 0.f);

#pragma unroll
        for (int v = 0; v < 4; v++) {
            float4 b = ld4s(b2p + 4 * v);
            setv4(&h[0][4 * v], b);
            setv4(&h[1][4 * v], b);
        }
#pragma unroll
        for (int k = 0; k < 16; k++) {
            float t0 = t[0][k], t1 = t[1][k];
#pragma unroll
            for (int v = 0; v < 4; v++) {
                float4 w = ld4s(w2p + k * 16 + 4 * v);
                addv4(&h[0][4 * v], t0, w);
                addv4(&h[1][4 * v], t1, w);
            }
        }
    }

    // ---- two GINE blocks ----
    gine_ln_relu2(h, e, lane, node,
                  S + L1_W, S + L1_B, S + M1_W1, S + M1_B1, S + M1_W2, S + M1_B2);
    gine_ln_relu2(h, e, lane, node,
                  S + L2_W, S + L2_B, S + M2_W1, S + M2_B1, S + M2_W2, S + M2_B2);

    // ---- pooling (mean + max over the 4 lanes of the graph) + LN ----
    float g[2][32];
#pragma unroll
    for (int nv = 0; nv < 2; nv++) {
#pragma unroll
        for (int d = 0; d < 16; d++) {
            float s = h[nv][d];
            s += __shfl_xor_sync(0xffffffffu, s, 1);
            s += __shfl_xor_sync(0xffffffffu, s, 2);
            float mx = h[nv][d];
            mx = fmaxf(mx, __shfl_xor_sync(0xffffffffu, mx, 1));
            mx = fmaxf(mx, __shfl_xor_sync(0xffffffffu, mx, 2));
            g[nv][d] = s * 0.25f;
            g[nv][16 + d] = mx;
        }
        float mean = 0.f;
#pragma unroll
        for (int d = 0; d < 32; d++) mean += g[nv][d];
        mean *= (1.f / 32.f);
        float var = 0.f;
#pragma unroll
        for (int d = 0; d < 32; d++) { float dd = g[nv][d] - mean; var = fmaf(dd, dd, var); }
        var *= (1.f / 32.f);
        float inv = rsqrtf(var + 1e-5f);
#pragma unroll
        for (int d = 0; d < 32; d++) g[nv][d] = (g[nv][d] - mean) * inv;
    }

    // ---- FC head: 32 -> 64 -> 1; each node owns 16 hidden units ----
    float acc0 = 0.f, acc1 = 0.f;
#pragma unroll
    for (int uv = 0; uv < 4; uv++) {
        float4 bb = ld4s(S + FC_B1 + node * 16 + uv * 4);
        float a0[4] = {bb.x, bb.y, bb.z, bb.w};
        float a1[4] = {bb.x, bb.y, bb.z, bb.w};
#pragma unroll
        for (int k = 0; k < 32; k++) {
            float4 w = ld4s(S + FC_W1 + k * 64 + node * 16 + uv * 4);
            addv4(a0, g[0][k], w);
            addv4(a1, g[1][k], w);
        }
        float4 wv = ld4s(S + FC_W2 + node * 16 + uv * 4);
        acc0 = fmaf(fmaxf(a0[0], 0.f), wv.x, acc0);
        acc0 = fmaf(fmaxf(a0[1], 0.f), wv.y, acc0);
        acc0 = fmaf(fmaxf(a0[2], 0.f), wv.z, acc0);
        acc0 = fmaf(fmaxf(a0[3], 0.f), wv.w, acc0);
        acc1 = fmaf(fmaxf(a1[0], 0.f), wv.x, acc1);
        acc1 = fmaf(fmaxf(a1[1], 0.f), wv.y, acc1);
        acc1 = fmaf(fmaxf(a1[2], 0.f), wv.z, acc1);
        acc1 = fmaf(fmaxf(a1[3], 0.f), wv.w, acc1);
    }
    acc0 += __shfl_xor_sync(0xffffffffu, acc0, 1);
    acc0 += __shfl_xor_sync(0xffffffffu, acc0, 2);
    acc1 += __shfl_xor_sync(0xffffffffu, acc1, 1);
    acc1 += __shfl_xor_sync(0xffffffffu, acc1, 2);

    if (node == 0) {
        if (v0) p.out[g0] = acc0 + fcb2;
        if (v1) p.out[g1] = acc1 + fcb2;
    }
}

extern "C" void kernel_launch(void* const* d_in, const int* in_sizes, int n_in,
                              void* d_out, int out_size)
{
    Params p;
    p.x  = (const float*)d_in[0];
    p.ea = (const float*)d_in[1];
    for (int i = 0; i < 24; i++) p.w[i] = (const float*)d_in[2 + i];
    p.out = (float*)d_out;
    p.G = in_sizes[0] / 20;            // x is [G*4, 5]

    // 16 graphs per warp, 8 warps per block -> 128 graphs per block
    int blocks = (p.G + 127) / 128;
    if (blocks < 1) blocks = 1;
    gnn_kernel<<<blocks, NTHREADS>>>(p);
}

// round 4
// speedup vs baseline: 12.8064x; 1.5757x over previous
#include <cuda_runtime.h>

// Fixed problem structure:
//   4 nodes/graph (nodes 0..2 = jet, node 3 = muon)
//   12 directed edges/graph, edge (i,j) index within graph = 3*i + (j - (j>i))
//   H = 16, MH = 64.
// Mapping: warp = 8 groups of 4 lanes; group j handles graphs base+j and base+j+8
// (NV=2), so every shared-memory weight load feeds 2 graphs x 4 outputs of FMA.

#define NTHREADS 256

// ---- shared memory layout (floats) ----
#define JE_W1 0      // 80
#define JE_B1 80     // 16
#define JE_W2 96     // 256
#define JE_B2 352    // 16
#define MU_W1 368    // 80
#define MU_B1 448    // 16
#define MU_W2 464    // 256
#define MU_B2 720    // 16
#define L1_W  736    // 64
#define L1_B  800    // 16
#define M1_W1 816    // 1024
#define M1_B1 1840   // 64
#define M1_W2 1904   // 1024
#define M1_B2 2928   // 16
#define L2_W  2944   // 64
#define L2_B  3008   // 16
#define M2_W1 3024   // 1024
#define M2_B1 4048   // 64
#define M2_W2 4112   // 1024
#define M2_B2 5136   // 16
#define FC_W1 5152   // 2048
#define FC_B1 7200   // 64
#define FC_W2 7264   // 64
#define SMEM_FLOATS 7328

struct Params {
    const float* x;
    const float* ea;
    const float* w[24];   // je_w1..fc_b2 in metadata order
    float* out;
    int G;
};

__device__ __forceinline__ float4 ld4s(const float* p) {
    return *reinterpret_cast<const float4*>(p);
}

__device__ __forceinline__ void addv4(float* acc, float s, float4 w) {
    acc[0] = fmaf(s, w.x, acc[0]);
    acc[1] = fmaf(s, w.y, acc[1]);
    acc[2] = fmaf(s, w.z, acc[2]);
    acc[3] = fmaf(s, w.w, acc[3]);
}

__device__ __forceinline__ void setv4(float* dst, float4 b) {
    dst[0] = b.x; dst[1] = b.y; dst[2] = b.z; dst[3] = b.w;
}

// one GINE layer + LN + relu for 2 graphs; h updated in place.
// Edge attrs are reloaded from global (L1/L2 hits on layer 2) to save registers.
__device__ __forceinline__ void gine_ln_relu2(
    float h[2][16], int lane, int node,
    const float* __restrict__ eb0, const float* __restrict__ eb1,
    const float* lw, const float* lb,
    const float* w1, const float* b1,
    const float* w2, const float* b2)
{
    float agg[2][16];
#pragma unroll
    for (int nv = 0; nv < 2; nv++)
#pragma unroll
        for (int d = 0; d < 16; d++) agg[nv][d] = 0.f;

#pragma unroll
    for (int m = 1; m < 4; m++) {
        int src = (node + m) & 3;
        int eidx = src * 3 + node - (node > src ? 1 : 0);
        float4 e0 = __ldg(reinterpret_cast<const float4*>(eb0 + eidx * 4));
        float4 e1 = __ldg(reinterpret_cast<const float4*>(eb1 + eidx * 4));
        float ev0[4] = {e0.x, e0.y, e0.z, e0.w};
        float ev1[4] = {e1.x, e1.y, e1.z, e1.w};
        int sl = (lane & ~3) | src;

        // message in two 8-wide halves to cap live registers
#pragma unroll
        for (int half = 0; half < 2; half++) {
            float msg[2][8];
#pragma unroll
            for (int v = 0; v < 2; v++) {
                float4 b = ld4s(lb + half * 8 + 4 * v);
                setv4(&msg[0][4 * v], b);
                setv4(&msg[1][4 * v], b);
            }
#pragma unroll
            for (int k = 0; k < 4; k++) {
#pragma unroll
                for (int v = 0; v < 2; v++) {
                    float4 w = ld4s(lw + k * 16 + half * 8 + 4 * v);
                    addv4(&msg[0][4 * v], ev0[k], w);
                    addv4(&msg[1][4 * v], ev1[k], w);
                }
            }
#pragma unroll
            for (int d = 0; d < 8; d++) {
                int dd = half * 8 + d;
                float hs0 = __shfl_sync(0xffffffffu, h[0][dd], sl);
                float hs1 = __shfl_sync(0xffffffffu, h[1][dd], sl);
                agg[0][dd] += fmaxf(msg[0][d] + hs0, 0.f);
                agg[1][dd] += fmaxf(msg[1][d] + hs1, 0.f);
            }
        }
    }

    // in-place: h becomes the MLP input (h + agg)
#pragma unroll
    for (int nv = 0; nv < 2; nv++)
#pragma unroll
        for (int d = 0; d < 16; d++) h[nv][d] += agg[nv][d];

    float out[2][16];
#pragma unroll
    for (int v = 0; v < 4; v++) {
        float4 b = ld4s(b2 + 4 * v);
        setv4(&out[0][4 * v], b);
        setv4(&out[1][4 * v], b);
    }

    // 8 chunks of 8 hidden units: hid accumulators stay small
#pragma unroll
    for (int c = 0; c < 8; c++) {
        float hid[2][8];
#pragma unroll
        for (int v = 0; v < 2; v++) {
            float4 b = ld4s(b1 + c * 8 + 4 * v);
            setv4(&hid[0][4 * v], b);
            setv4(&hid[1][4 * v], b);
        }
#pragma unroll
        for (int k = 0; k < 16; k++) {
            float x0 = h[0][k];
            float x1 = h[1][k];
#pragma unroll
            for (int v = 0; v < 2; v++) {
                float4 w = ld4s(w1 + k * 64 + c * 8 + 4 * v);
                addv4(&hid[0][4 * v], x0, w);
                addv4(&hid[1][4 * v], x1, w);
            }
        }
#pragma unroll
        for (int nv = 0; nv < 2; nv++)
#pragma unroll
            for (int u = 0; u < 8; u++) hid[nv][u] = fmaxf(hid[nv][u], 0.f);
#pragma unroll
        for (int u = 0; u < 8; u++) {
            float h0 = hid[0][u];
            float h1 = hid[1][u];
            const float* r = w2 + (c * 8 + u) * 16;
#pragma unroll
            for (int v = 0; v < 4; v++) {
                float4 w = ld4s(r + 4 * v);
                addv4(&out[0][4 * v], h0, w);
                addv4(&out[1][4 * v], h1, w);
            }
        }
    }

    // LayerNorm (ddof=0) + relu -> back into h
#pragma unroll
    for (int nv = 0; nv < 2; nv++) {
        float mean = 0.f;
#pragma unroll
        for (int d = 0; d < 16; d++) mean += out[nv][d];
        mean *= (1.f / 16.f);
        float var = 0.f;
#pragma unroll
        for (int d = 0; d < 16; d++) { float dd = out[nv][d] - mean; var = fmaf(dd, dd, var); }
        var *= (1.f / 16.f);
        float inv = rsqrtf(var + 1e-5f);
#pragma unroll
        for (int d = 0; d < 16; d++) h[nv][d] = fmaxf((out[nv][d] - mean) * inv, 0.f);
    }
}

__global__ void __launch_bounds__(NTHREADS, 2)
gnn_kernel(Params p)
{
    __shared__ float S[SMEM_FLOATS];

    // stage all weights into shared
    {
        const int sizes[23] = {80,16,256,16, 80,16,256,16,
                               64,16,1024,64,1024,16,
                               64,16,1024,64,1024,16,
                               2048,64,64};
        const int offs[23]  = {JE_W1,JE_B1,JE_W2,JE_B2, MU_W1,MU_B1,MU_W2,MU_B2,
                               L1_W,L1_B,M1_W1,M1_B1,M1_W2,M1_B2,
                               L2_W,L2_B,M2_W1,M2_B1,M2_W2,M2_B2,
                               FC_W1,FC_B1,FC_W2};
        for (int a = 0; a < 23; a++) {
            const float* src = p.w[a];
            float* dst = S + offs[a];
            int n = sizes[a];
            for (int i = threadIdx.x; i < n; i += NTHREADS) dst[i] = src[i];
        }
    }
    __syncthreads();

    int tid = threadIdx.x;
    int lane = tid & 31;
    int node = lane & 3;
    int group = lane >> 2;
    int warpG = (int)((blockIdx.x * (unsigned)NTHREADS + tid) >> 5);

    if (warpG * 16 >= p.G) return;   // warp-uniform

    int g0 = warpG * 16 + group;
    int g1 = g0 + 8;
    bool v0 = g0 < p.G;
    bool v1 = g1 < p.G;
    int gc0 = v0 ? g0 : (p.G - 1);
    int gc1 = v1 ? g1 : (p.G - 1);

    const float* eb0 = p.ea + (long long)gc0 * 48;
    const float* eb1 = p.ea + (long long)gc1 * 48;

    // ---- heterogeneous encoder ----
    const float* w1p = (node == 3) ? (S + MU_W1) : (S + JE_W1);
    const float* b1p = (node == 3) ? (S + MU_B1) : (S + JE_B1);
    const float* w2p = (node == 3) ? (S + MU_W2) : (S + JE_W2);
    const float* b2p = (node == 3) ? (S + MU_B2) : (S + JE_B2);

    float h[2][16];
    {
        float xin[2][5];
        const float* xr0 = p.x + (long long)(gc0 * 4 + node) * 5;
        const float* xr1 = p.x + (long long)(gc1 * 4 + node) * 5;
#pragma unroll
        for (int k = 0; k < 5; k++) { xin[0][k] = __ldg(xr0 + k); xin[1][k] = __ldg(xr1 + k); }

        float t[2][16];
#pragma unroll
        for (int v = 0; v < 4; v++) {
            float4 b = ld4s(b1p + 4 * v);
            setv4(&t[0][4 * v], b);
            setv4(&t[1][4 * v], b);
        }
#pragma unroll
        for (int k = 0; k < 5; k++) {
            float x0 = xin[0][k], x1 = xin[1][k];
#pragma unroll
            for (int v = 0; v < 4; v++) {
                float4 w = ld4s(w1p + k * 16 + 4 * v);
                addv4(&t[0][4 * v], x0, w);
                addv4(&t[1][4 * v], x1, w);
            }
        }
#pragma unroll
        for (int nv = 0; nv < 2; nv++)
#pragma unroll
            for (int u = 0; u < 16; u++) t[nv][u] = fmaxf(t[nv][u], 0.f);

#pragma unroll
        for (int v = 0; v < 4; v++) {
            float4 b = ld4s(b2p + 4 * v);
            setv4(&h[0][4 * v], b);
            setv4(&h[1][4 * v], b);
        }
#pragma unroll
        for (int k = 0; k < 16; k++) {
            float t0 = t[0][k], t1 = t[1][k];
#pragma unroll
            for (int v = 0; v < 4; v++) {
                float4 w = ld4s(w2p + k * 16 + 4 * v);
                addv4(&h[0][4 * v], t0, w);
                addv4(&h[1][4 * v], t1, w);
            }
        }
    }

    // ---- two GINE blocks ----
    gine_ln_relu2(h, lane, node, eb0, eb1,
                  S + L1_W, S + L1_B, S + M1_W1, S + M1_B1, S + M1_W2, S + M1_B2);
    gine_ln_relu2(h, lane, node, eb0, eb1,
                  S + L2_W, S + L2_B, S + M2_W1, S + M2_B1, S + M2_W2, S + M2_B2);

    // ---- pooling (mean + max over the 4 lanes of the graph) + LN ----
    float g[2][32];
#pragma unroll
    for (int nv = 0; nv < 2; nv++) {
#pragma unroll
        for (int d = 0; d < 16; d++) {
            float s = h[nv][d];
            s += __shfl_xor_sync(0xffffffffu, s, 1);
            s += __shfl_xor_sync(0xffffffffu, s, 2);
            float mx = h[nv][d];
            mx = fmaxf(mx, __shfl_xor_sync(0xffffffffu, mx, 1));
            mx = fmaxf(mx, __shfl_xor_sync(0xffffffffu, mx, 2));
            g[nv][d] = s * 0.25f;
            g[nv][16 + d] = mx;
        }
        float mean = 0.f;
#pragma unroll
        for (int d = 0; d < 32; d++) mean += g[nv][d];
        mean *= (1.f / 32.f);
        float var = 0.f;
#pragma unroll
        for (int d = 0; d < 32; d++) { float dd = g[nv][d] - mean; var = fmaf(dd, dd, var); }
        var *= (1.f / 32.f);
        float inv = rsqrtf(var + 1e-5f);
#pragma unroll
        for (int d = 0; d < 32; d++) g[nv][d] = (g[nv][d] - mean) * inv;
    }

    // ---- FC head: 32 -> 64 -> 1; each node owns 16 hidden units ----
    float acc0 = 0.f, acc1 = 0.f;
#pragma unroll
    for (int uv = 0; uv < 4; uv++) {
        float4 bb = ld4s(S + FC_B1 + node * 16 + uv * 4);
        float a0[4] = {bb.x, bb.y, bb.z, bb.w};
        float a1[4] = {bb.x, bb.y, bb.z, bb.w};
#pragma unroll
        for (int k = 0; k < 32; k++) {
            float4 w = ld4s(S + FC_W1 + k * 64 + node * 16 + uv * 4);
            addv4(a0, g[0][k], w);
            addv4(a1, g[1][k], w);
        }
        float4 wv = ld4s(S + FC_W2 + node * 16 + uv * 4);
        acc0 = fmaf(fmaxf(a0[0], 0.f), wv.x, acc0);
        acc0 = fmaf(fmaxf(a0[1], 0.f), wv.y, acc0);
        acc0 = fmaf(fmaxf(a0[2], 0.f), wv.z, acc0);
        acc0 = fmaf(fmaxf(a0[3], 0.f), wv.w, acc0);
        acc1 = fmaf(fmaxf(a1[0], 0.f), wv.x, acc1);
        acc1 = fmaf(fmaxf(a1[1], 0.f), wv.y, acc1);
        acc1 = fmaf(fmaxf(a1[2], 0.f), wv.z, acc1);
        acc1 = fmaf(fmaxf(a1[3], 0.f), wv.w, acc1);
    }
    acc0 += __shfl_xor_sync(0xffffffffu, acc0, 1);
    acc0 += __shfl_xor_sync(0xffffffffu, acc0, 2);
    acc1 += __shfl_xor_sync(0xffffffffu, acc1, 1);
    acc1 += __shfl_xor_sync(0xffffffffu, acc1, 2);

    const float fcb2 = __ldg(p.w[23]);
    if (node == 0) {
        if (v0) p.out[g0] = acc0 + fcb2;
        if (v1) p.out[g1] = acc1 + fcb2;
    }
}

extern "C" void kernel_launch(void* const* d_in, const int* in_sizes, int n_in,
                              void* d_out, int out_size)
{
    Params p;
    p.x  = (const float*)d_in[0];
    p.ea = (const float*)d_in[1];
    for (int i = 0; i < 24; i++) p.w[i] = (const float*)d_in[2 + i];
    p.out = (float*)d_out;
    p.G = in_sizes[0] / 20;            // x is [G*4, 5]

    // 16 graphs per warp, 8 warps per block -> 128 graphs per block
    int blocks = (p.G + 127) / 128;
    if (blocks < 1) blocks = 1;
    gnn_kernel<<<blocks, NTHREADS>>>(p);
}

// round 5
// speedup vs baseline: 16.4750x; 1.2865x over previous
#include <cuda_runtime.h>

// Fixed problem structure:
//   4 nodes/graph (nodes 0..2 = jet, node 3 = muon)
//   12 directed edges/graph, edge (i,j) index within graph = 3*i + (j - (j>i))
//   H = 16, MH = 64.
// Mapping: warp = 8 groups of 4 lanes; group j handles graphs base+j and base+j+8
// (NV=2). All inner products use packed f32x2 FFMA along the output-dim axis:
// weight pairs come straight out of shared-memory 16B loads.

#define NTHREADS 256

typedef unsigned long long u64;

// ---- shared memory layout (floats) ----
#define JE_W1 0      // 80
#define JE_B1 80     // 16
#define JE_W2 96     // 256
#define JE_B2 352    // 16
#define MU_W1 368    // 80
#define MU_B1 448    // 16
#define MU_W2 464    // 256
#define MU_B2 720    // 16
#define L1_W  736    // 64
#define L1_B  800    // 16
#define M1_W1 816    // 1024
#define M1_B1 1840   // 64
#define M1_W2 1904   // 1024
#define M1_B2 2928   // 16
#define L2_W  2944   // 64
#define L2_B  3008   // 16
#define M2_W1 3024   // 1024
#define M2_B1 4048   // 64
#define M2_W2 4112   // 1024
#define M2_B2 5136   // 16
#define FC_W1 5152   // 2048
#define FC_B1 7200   // 64
#define FC_W2 7264   // 64
#define SMEM_FLOATS 7328

struct Params {
    const float* x;
    const float* ea;
    const float* w[24];   // je_w1..fc_b2 in metadata order
    float* out;
    int G;
};

// ---- packed f32x2 helpers ----
__device__ __forceinline__ u64 pk(float lo, float hi) {
    u64 r; asm("mov.b64 %0,{%1,%2};" : "=l"(r) : "f"(lo), "f"(hi)); return r;
}
__device__ __forceinline__ void up(u64 v, float& lo, float& hi) {
    asm("mov.b64 {%0,%1},%2;" : "=f"(lo), "=f"(hi) : "l"(v));
}
__device__ __forceinline__ u64 f2(u64 a, u64 b, u64 c) {  // a*b+c elementwise
    u64 d; asm("fma.rn.f32x2 %0,%1,%2,%3;" : "=l"(d) : "l"(a), "l"(b), "l"(c)); return d;
}
__device__ __forceinline__ u64 a2(u64 a, u64 b) {
    u64 d; asm("add.rn.f32x2 %0,%1,%2;" : "=l"(d) : "l"(a), "l"(b)); return d;
}
__device__ __forceinline__ u64 r2(u64 a) {   // relu both halves
    float l, h; up(a, l, h);
    return pk(fmaxf(l, 0.f), fmaxf(h, 0.f));
}
__device__ __forceinline__ ulonglong2 ld2(const float* p) {  // LDS.128 -> 2 packed pairs
    return *reinterpret_cast<const ulonglong2*>(p);
}
__device__ __forceinline__ float4 ld4s(const float* p) {
    return *reinterpret_cast<const float4*>(p);
}

// one GINE layer + LN + relu for 2 graphs; h (scalars) updated in place.
__device__ __forceinline__ void gine2(
    float h[2][16], int lane, int node,
    const float* __restrict__ eb0, const float* __restrict__ eb1,
    const float* lw, const float* lb,
    const float* w1, const float* b1,
    const float* w2, const float* b2)
{
    // pack h into dim-pairs for shuffle/aggregate
    u64 hp[2][8], agg[2][8];
#pragma unroll
    for (int nv = 0; nv < 2; nv++)
#pragma unroll
        for (int j = 0; j < 8; j++) { hp[nv][j] = pk(h[nv][2*j], h[nv][2*j+1]); agg[nv][j] = 0ull; }

#pragma unroll
    for (int m = 1; m < 4; m++) {
        int src = (node + m) & 3;
        int eidx = src * 3 + node - (node > src ? 1 : 0);
        float4 e0 = __ldg(reinterpret_cast<const float4*>(eb0 + eidx * 4));
        float4 e1 = __ldg(reinterpret_cast<const float4*>(eb1 + eidx * 4));
        u64 ep0[4] = {pk(e0.x,e0.x), pk(e0.y,e0.y), pk(e0.z,e0.z), pk(e0.w,e0.w)};
        u64 ep1[4] = {pk(e1.x,e1.x), pk(e1.y,e1.y), pk(e1.z,e1.z), pk(e1.w,e1.w)};
        int sl = (lane & ~3) | src;

#pragma unroll
        for (int half = 0; half < 2; half++) {
            u64 msg[2][4];
            {
                ulonglong2 b = ld2(lb + half * 8);
                ulonglong2 b2v = ld2(lb + half * 8 + 4);
                msg[0][0] = b.x;  msg[0][1] = b.y;  msg[0][2] = b2v.x; msg[0][3] = b2v.y;
                msg[1][0] = b.x;  msg[1][1] = b.y;  msg[1][2] = b2v.x; msg[1][3] = b2v.y;
            }
#pragma unroll
            for (int k = 0; k < 4; k++) {
                ulonglong2 wa = ld2(lw + k * 16 + half * 8);
                ulonglong2 wb = ld2(lw + k * 16 + half * 8 + 4);
                u64 wv[4] = {wa.x, wa.y, wb.x, wb.y};
#pragma unroll
                for (int v = 0; v < 4; v++) {
                    msg[0][v] = f2(ep0[k], wv[v], msg[0][v]);
                    msg[1][v] = f2(ep1[k], wv[v], msg[1][v]);
                }
            }
#pragma unroll
            for (int v = 0; v < 4; v++) {
                int j = half * 4 + v;
                u64 hs0 = __shfl_sync(0xffffffffu, hp[0][j], sl);
                u64 hs1 = __shfl_sync(0xffffffffu, hp[1][j], sl);
                agg[0][j] = a2(agg[0][j], r2(a2(msg[0][v], hs0)));
                agg[1][j] = a2(agg[1][j], r2(a2(msg[1][v], hs1)));
            }
        }
    }

    // in = h + agg (unpack to scalars for broadcast multiplicands)
    float in[2][16];
#pragma unroll
    for (int nv = 0; nv < 2; nv++)
#pragma unroll
        for (int j = 0; j < 8; j++) {
            u64 s = a2(hp[nv][j], agg[nv][j]);
            up(s, in[nv][2*j], in[nv][2*j+1]);
        }

    u64 out[2][8];
    {
        ulonglong2 ba = ld2(b2), bb = ld2(b2 + 4), bc = ld2(b2 + 8), bd = ld2(b2 + 12);
        out[0][0]=ba.x; out[0][1]=ba.y; out[0][2]=bb.x; out[0][3]=bb.y;
        out[0][4]=bc.x; out[0][5]=bc.y; out[0][6]=bd.x; out[0][7]=bd.y;
#pragma unroll
        for (int j = 0; j < 8; j++) out[1][j] = out[0][j];
    }

    // 4 chunks of 16 hidden units
#pragma unroll
    for (int c = 0; c < 4; c++) {
        u64 hid[2][8];
        {
            ulonglong2 ba = ld2(b1 + c*16), bb = ld2(b1 + c*16 + 4);
            ulonglong2 bc = ld2(b1 + c*16 + 8), bd = ld2(b1 + c*16 + 12);
            hid[0][0]=ba.x; hid[0][1]=ba.y; hid[0][2]=bb.x; hid[0][3]=bb.y;
            hid[0][4]=bc.x; hid[0][5]=bc.y; hid[0][6]=bd.x; hid[0][7]=bd.y;
#pragma unroll
            for (int j = 0; j < 8; j++) hid[1][j] = hid[0][j];
        }
#pragma unroll
        for (int k = 0; k < 16; k++) {
            u64 x0 = pk(in[0][k], in[0][k]);
            u64 x1 = pk(in[1][k], in[1][k]);
            const float* r = w1 + k * 64 + c * 16;
            ulonglong2 wa = ld2(r), wb = ld2(r + 4), wc = ld2(r + 8), wd = ld2(r + 12);
            u64 wv[8] = {wa.x, wa.y, wb.x, wb.y, wc.x, wc.y, wd.x, wd.y};
#pragma unroll
            for (int j = 0; j < 8; j++) {
                hid[0][j] = f2(x0, wv[j], hid[0][j]);
                hid[1][j] = f2(x1, wv[j], hid[1][j]);
            }
        }
        // relu + second matmul: hidden units become scalar multiplicands
#pragma unroll
        for (int j = 0; j < 8; j++) {
            float u0a, u0b, u1a, u1b;
            up(hid[0][j], u0a, u0b);
            up(hid[1][j], u1a, u1b);
            u0a = fmaxf(u0a, 0.f); u0b = fmaxf(u0b, 0.f);
            u1a = fmaxf(u1a, 0.f); u1b = fmaxf(u1b, 0.f);
#pragma unroll
            for (int half = 0; half < 2; half++) {
                float s0 = half ? u0b : u0a;
                float s1 = half ? u1b : u1a;
                int u = c * 16 + 2 * j + half;
                const float* r = w2 + u * 16;
                ulonglong2 wa = ld2(r), wb = ld2(r + 4), wc = ld2(r + 8), wd = ld2(r + 12);
                u64 wv[8] = {wa.x, wa.y, wb.x, wb.y, wc.x, wc.y, wd.x, wd.y};
                u64 p0 = pk(s0, s0);
                u64 p1 = pk(s1, s1);
#pragma unroll
                for (int jj = 0; jj < 8; jj++) {
                    out[0][jj] = f2(p0, wv[jj], out[0][jj]);
                    out[1][jj] = f2(p1, wv[jj], out[1][jj]);
                }
            }
        }
    }

    // LayerNorm (ddof=0) + relu -> back into scalar h
#pragma unroll
    for (int nv = 0; nv < 2; nv++) {
        float o[16];
#pragma unroll
        for (int j = 0; j < 8; j++) up(out[nv][j], o[2*j], o[2*j+1]);
        float mean = 0.f;
#pragma unroll
        for (int d = 0; d < 16; d++) mean += o[d];
        mean *= (1.f / 16.f);
        float var = 0.f;
#pragma unroll
        for (int d = 0; d < 16; d++) { float dd = o[d] - mean; var = fmaf(dd, dd, var); }
        var *= (1.f / 16.f);
        float inv = rsqrtf(var + 1e-5f);
#pragma unroll
        for (int d = 0; d < 16; d++) h[nv][d] = fmaxf((o[d] - mean) * inv, 0.f);
    }
}

__global__ void __launch_bounds__(NTHREADS, 2)
gnn_kernel(Params p)
{
    __shared__ float S[SMEM_FLOATS];

    // stage all weights into shared
    {
        const int sizes[23] = {80,16,256,16, 80,16,256,16,
                               64,16,1024,64,1024,16,
                               64,16,1024,64,1024,16,
                               2048,64,64};
        const int offs[23]  = {JE_W1,JE_B1,JE_W2,JE_B2, MU_W1,MU_B1,MU_W2,MU_B2,
                               L1_W,L1_B,M1_W1,M1_B1,M1_W2,M1_B2,
                               L2_W,L2_B,M2_W1,M2_B1,M2_W2,M2_B2,
                               FC_W1,FC_B1,FC_W2};
        for (int a = 0; a < 23; a++) {
            const float* src = p.w[a];
            float* dst = S + offs[a];
            int n = sizes[a];
            for (int i = threadIdx.x; i < n; i += NTHREADS) dst[i] = src[i];
        }
    }
    __syncthreads();

    int tid = threadIdx.x;
    int lane = tid & 31;
    int node = lane & 3;
    int group = lane >> 2;
    int warpG = (int)((blockIdx.x * (unsigned)NTHREADS + tid) >> 5);

    if (warpG * 16 >= p.G) return;   // warp-uniform

    int g0 = warpG * 16 + group;
    int g1 = g0 + 8;
    bool v0 = g0 < p.G;
    bool v1 = g1 < p.G;
    int gc0 = v0 ? g0 : (p.G - 1);
    int gc1 = v1 ? g1 : (p.G - 1);

    const float* eb0 = p.ea + (long long)gc0 * 48;
    const float* eb1 = p.ea + (long long)gc1 * 48;

    // ---- heterogeneous encoder ----
    const float* w1p = (node == 3) ? (S + MU_W1) : (S + JE_W1);
    const float* b1p = (node == 3) ? (S + MU_B1) : (S + JE_B1);
    const float* w2p = (node == 3) ? (S + MU_W2) : (S + JE_W2);
    const float* b2p = (node == 3) ? (S + MU_B2) : (S + JE_B2);

    float h[2][16];
    {
        float xin[2][5];
        const float* xr0 = p.x + (long long)(gc0 * 4 + node) * 5;
        const float* xr1 = p.x + (long long)(gc1 * 4 + node) * 5;
#pragma unroll
        for (int k = 0; k < 5; k++) { xin[0][k] = __ldg(xr0 + k); xin[1][k] = __ldg(xr1 + k); }

        u64 tv[2][8];
        {
            ulonglong2 ba = ld2(b1p), bb = ld2(b1p + 4), bc = ld2(b1p + 8), bd = ld2(b1p + 12);
            tv[0][0]=ba.x; tv[0][1]=ba.y; tv[0][2]=bb.x; tv[0][3]=bb.y;
            tv[0][4]=bc.x; tv[0][5]=bc.y; tv[0][6]=bd.x; tv[0][7]=bd.y;
#pragma unroll
            for (int j = 0; j < 8; j++) tv[1][j] = tv[0][j];
        }
#pragma unroll
        for (int k = 0; k < 5; k++) {
            u64 x0 = pk(xin[0][k], xin[0][k]);
            u64 x1 = pk(xin[1][k], xin[1][k]);
            const float* r = w1p + k * 16;
            ulonglong2 wa = ld2(r), wb = ld2(r + 4), wc = ld2(r + 8), wd = ld2(r + 12);
            u64 wv[8] = {wa.x, wa.y, wb.x, wb.y, wc.x, wc.y, wd.x, wd.y};
#pragma unroll
            for (int j = 0; j < 8; j++) {
                tv[0][j] = f2(x0, wv[j], tv[0][j]);
                tv[1][j] = f2(x1, wv[j], tv[1][j]);
            }
        }
        float t[2][16];
#pragma unroll
        for (int nv = 0; nv < 2; nv++)
#pragma unroll
            for (int j = 0; j < 8; j++) {
                up(tv[nv][j], t[nv][2*j], t[nv][2*j+1]);
                t[nv][2*j]   = fmaxf(t[nv][2*j],   0.f);
                t[nv][2*j+1] = fmaxf(t[nv][2*j+1], 0.f);
            }

        u64 hv[2][8];
        {
            ulonglong2 ba = ld2(b2p), bb = ld2(b2p + 4), bc = ld2(b2p + 8), bd = ld2(b2p + 12);
            hv[0][0]=ba.x; hv[0][1]=ba.y; hv[0][2]=bb.x; hv[0][3]=bb.y;
            hv[0][4]=bc.x; hv[0][5]=bc.y; hv[0][6]=bd.x; hv[0][7]=bd.y;
#pragma unroll
            for (int j = 0; j < 8; j++) hv[1][j] = hv[0][j];
        }
#pragma unroll
        for (int k = 0; k < 16; k++) {
            u64 t0 = pk(t[0][k], t[0][k]);
            u64 t1 = pk(t[1][k], t[1][k]);
            const float* r = w2p + k * 16;
            ulonglong2 wa = ld2(r), wb = ld2(r + 4), wc = ld2(r + 8), wd = ld2(r + 12);
            u64 wv[8] = {wa.x, wa.y, wb.x, wb.y, wc.x, wc.y, wd.x, wd.y};
#pragma unroll
            for (int j = 0; j < 8; j++) {
                hv[0][j] = f2(t0, wv[j], hv[0][j]);
                hv[1][j] = f2(t1, wv[j], hv[1][j]);
            }
        }
#pragma unroll
        for (int nv = 0; nv < 2; nv++)
#pragma unroll
            for (int j = 0; j < 8; j++) up(hv[nv][j], h[nv][2*j], h[nv][2*j+1]);
    }

    // ---- two GINE blocks ----
    gine2(h, lane, node, eb0, eb1,
          S + L1_W, S + L1_B, S + M1_W1, S + M1_B1, S + M1_W2, S + M1_B2);
    gine2(h, lane, node, eb0, eb1,
          S + L2_W, S + L2_B, S + M2_W1, S + M2_B1, S + M2_W2, S + M2_B2);

    // ---- pooling (mean + max over the 4 lanes of the graph) + LN ----
    float g[2][32];
#pragma unroll
    for (int nv = 0; nv < 2; nv++) {
#pragma unroll
        for (int d = 0; d < 16; d++) {
            float s = h[nv][d];
            s += __shfl_xor_sync(0xffffffffu, s, 1);
            s += __shfl_xor_sync(0xffffffffu, s, 2);
            float mx = h[nv][d];
            mx = fmaxf(mx, __shfl_xor_sync(0xffffffffu, mx, 1));
            mx = fmaxf(mx, __shfl_xor_sync(0xffffffffu, mx, 2));
            g[nv][d] = s * 0.25f;
            g[nv][16 + d] = mx;
        }
        float mean = 0.f;
#pragma unroll
        for (int d = 0; d < 32; d++) mean += g[nv][d];
        mean *= (1.f / 32.f);
        float var = 0.f;
#pragma unroll
        for (int d = 0; d < 32; d++) { float dd = g[nv][d] - mean; var = fmaf(dd, dd, var); }
        var *= (1.f / 32.f);
        float inv = rsqrtf(var + 1e-5f);
#pragma unroll
        for (int d = 0; d < 32; d++) g[nv][d] = (g[nv][d] - mean) * inv;
    }

    // ---- FC head: 32 -> 64 -> 1; each node owns 16 hidden units (packed) ----
    u64 av[2][8];
    {
        const float* r = S + FC_B1 + node * 16;
        ulonglong2 ba = ld2(r), bb = ld2(r + 4), bc = ld2(r + 8), bd = ld2(r + 12);
        av[0][0]=ba.x; av[0][1]=ba.y; av[0][2]=bb.x; av[0][3]=bb.y;
        av[0][4]=bc.x; av[0][5]=bc.y; av[0][6]=bd.x; av[0][7]=bd.y;
#pragma unroll
        for (int j = 0; j < 8; j++) av[1][j] = av[0][j];
    }
#pragma unroll
    for (int k = 0; k < 32; k++) {
        u64 g0p = pk(g[0][k], g[0][k]);
        u64 g1p = pk(g[1][k], g[1][k]);
        const float* r = S + FC_W1 + k * 64 + node * 16;
        ulonglong2 wa = ld2(r), wb = ld2(r + 4), wc = ld2(r + 8), wd = ld2(r + 12);
        u64 wv[8] = {wa.x, wa.y, wb.x, wb.y, wc.x, wc.y, wd.x, wd.y};
#pragma unroll
        for (int j = 0; j < 8; j++) {
            av[0][j] = f2(g0p, wv[j], av[0][j]);
            av[1][j] = f2(g1p, wv[j], av[1][j]);
        }
    }
    float acc0 = 0.f, acc1 = 0.f;
#pragma unroll
    for (int j = 0; j < 8; j++) {
        float2 w2v = *reinterpret_cast<const float2*>(S + FC_W2 + node * 16 + 2 * j);
        float a, b;
        up(av[0][j], a, b);
        acc0 = fmaf(fmaxf(a, 0.f), w2v.x, acc0);
        acc0 = fmaf(fmaxf(b, 0.f), w2v.y, acc0);
        up(av[1][j], a, b);
        acc1 = fmaf(fmaxf(a, 0.f), w2v.x, acc1);
        acc1 = fmaf(fmaxf(b, 0.f), w2v.y, acc1);
    }
    acc0 += __shfl_xor_sync(0xffffffffu, acc0, 1);
    acc0 += __shfl_xor_sync(0xffffffffu, acc0, 2);
    acc1 += __shfl_xor_sync(0xffffffffu, acc1, 1);
    acc1 += __shfl_xor_sync(0xffffffffu, acc1, 2);

    const float fcb2 = __ldg(p.w[23]);
    if (node == 0) {
        if (v0) p.out[g0] = acc0 + fcb2;
        if (v1) p.out[g1] = acc1 + fcb2;
    }
}

extern "C" void kernel_launch(void* const* d_in, const int* in_sizes, int n_in,
                              void* d_out, int out_size)
{
    Params p;
    p.x  = (const float*)d_in[0];
    p.ea = (const float*)d_in[1];
    for (int i = 0; i < 24; i++) p.w[i] = (const float*)d_in[2 + i];
    p.out = (float*)d_out;
    p.G = in_sizes[0] / 20;            // x is [G*4, 5]

    // 16 graphs per warp, 8 warps per block -> 128 graphs per block
    int blocks = (p.G + 127) / 128;
    if (blocks < 1) blocks = 1;
    gnn_kernel<<<blocks, NTHREADS>>>(p);
}